// round 4
// baseline (speedup 1.0000x reference)
#include <cuda_runtime.h>

#define TT 4096
#define EE 64
#define HH 4096
#define TKK 8
#define NGEMM 64          // GEMM-role blocks (one 64-token tile each)
#define NTHR  512

// ---- scratch (device globals; no allocations allowed) ----
__device__ int   g_id[TT * TKK];    // top-8 expert ids per token
__device__ float g_pr[TT * TKK];    // router prob for each selected expert
__device__ int   g_pos[TT * TKK];   // dispatch position within expert capacity
__device__ int   g_done;            // last-block counter (reset by kC)

// ============================================================================
// Kernel A: fused  [zero d_out]  ||  [GEMM + softmax + top-8 + positions]
//   bid <  NGEMM : GEMM role. 64tok x 64exp tile, 512 thr, each thread a
//                  2tok x 4exp register tile (f32x2 FMA, double chunk-accum).
//                  The LAST GEMM block to finish also computes per-(k,e)
//                  bases and within-expert dispatch positions (B0+B1).
//   bid >= NGEMM : zero role, grid-stride float4 streaming fill of d_out.
// ============================================================================
__global__ void __launch_bounds__(NTHR) kA(const float* __restrict__ x,
                                           const float* __restrict__ w,
                                           float* __restrict__ out,
                                           long long outn)
{
    __shared__ __align__(16) unsigned char sraw[2 * 64 * 68 * 4];  // 34816 B
    __shared__ int s_last;
    const int bid = blockIdx.x, tid = threadIdx.x;

    if (bid >= NGEMM) {
        // -------- zero role --------
        long long zid = bid - NGEMM;
        float4 z = make_float4(0.f, 0.f, 0.f, 0.f);
        float4* o4 = (float4*)out;
        long long n4 = outn >> 2;                       // outn % 4 == 0
        long long stride = (long long)(gridDim.x - NGEMM) * NTHR;
        for (long long i = zid * NTHR + tid; i < n4; i += stride)
            __stcs(o4 + i, z);
        return;
    }

    // -------- GEMM role --------
    float (*Xs)[68] = (float(*)[68])sraw;                    // [hh][token]
    float (*Ws)[68] = (float(*)[68])(sraw + 64 * 68 * 4);    // [hh][expert]

    const int t0 = bid * 64;
    const int tx = tid & 15;         // expert quad: experts tx*4..tx*4+3
    const int ty = tid >> 4;         // token pair:  tokens ty*2..ty*2+1

    double acc[8];                   // [t][e] t<2, e<4
    #pragma unroll
    for (int i = 0; i < 8; i++) acc[i] = 0.0;

    for (int h0 = 0; h0 < HH; h0 += 64) {
        #pragma unroll
        for (int r = 0; r < 8; r++) {
            int i = r * NTHR + tid;
            int hh = i & 63, t = i >> 6;                 // t: token / expert id
            Xs[hh][t] = x[(long long)(t0 + t) * HH + h0 + hh];
            Ws[hh][t] = w[(long long)t * HH + h0 + hh];
        }
        __syncthreads();

        unsigned long long c[4];     // (e0,e1),(e2,e3) per token
        #pragma unroll
        for (int i = 0; i < 4; i++) c[i] = 0ull;

        #pragma unroll 16
        for (int kk = 0; kk < 64; kk++) {
            float2 xv = *(const float2*)&Xs[kk][ty * 2];
            ulonglong2 wv = *(const ulonglong2*)&Ws[kk][tx * 4];
            unsigned long long xx0, xx1;
            asm("mov.b64 %0, {%1, %1};" : "=l"(xx0) : "r"(__float_as_uint(xv.x)));
            asm("mov.b64 %0, {%1, %1};" : "=l"(xx1) : "r"(__float_as_uint(xv.y)));
            asm("fma.rn.f32x2 %0, %1, %2, %0;" : "+l"(c[0]) : "l"(wv.x), "l"(xx0));
            asm("fma.rn.f32x2 %0, %1, %2, %0;" : "+l"(c[1]) : "l"(wv.y), "l"(xx0));
            asm("fma.rn.f32x2 %0, %1, %2, %0;" : "+l"(c[2]) : "l"(wv.x), "l"(xx1));
            asm("fma.rn.f32x2 %0, %1, %2, %0;" : "+l"(c[3]) : "l"(wv.y), "l"(xx1));
        }

        #pragma unroll
        for (int t = 0; t < 2; t++)
            #pragma unroll
            for (int j = 0; j < 2; j++) {
                unsigned lo, hi;
                asm("mov.b64 {%0, %1}, %2;" : "=r"(lo), "=r"(hi) : "l"(c[t * 2 + j]));
                acc[t * 4 + j * 2 + 0] += (double)__uint_as_float(lo);
                acc[t * 4 + j * 2 + 1] += (double)__uint_as_float(hi);
            }
        __syncthreads();
    }

    // ---- logits tile to smem (overlay) ----
    float (*lg)[65] = (float(*)[65])sraw;
    __syncthreads();
    #pragma unroll
    for (int t = 0; t < 2; t++)
        #pragma unroll
        for (int e = 0; e < 4; e++)
            lg[ty * 2 + t][tx * 4 + e] = (float)acc[t * 4 + e];
    __syncthreads();

    // ---- softmax + iterative top-8 (16 warps x 4 tokens) ----
    const int wrp = tid >> 5, lane = tid & 31;
    for (int tt = 0; tt < 4; tt++) {
        int t = wrp * 4 + tt;
        float v0 = lg[t][lane], v1 = lg[t][lane + 32];

        float m = fmaxf(v0, v1);
        #pragma unroll
        for (int o = 16; o; o >>= 1) m = fmaxf(m, __shfl_xor_sync(0xffffffffu, m, o));

        float z = __expf(v0 - m) + __expf(v1 - m);
        #pragma unroll
        for (int o = 16; o; o >>= 1) z += __shfl_xor_sync(0xffffffffu, z, o);

        float s0 = v0, s1 = v1;
        int   wid_[TKK];
        float wex[TKK];
        float ssum = 0.f;

        #pragma unroll
        for (int k = 0; k < TKK; k++) {
            unsigned b0 = __float_as_uint(s0);
            b0 ^= (b0 & 0x80000000u) ? 0xFFFFFFFFu : 0x80000000u;
            unsigned b1 = __float_as_uint(s1);
            b1 ^= (b1 & 0x80000000u) ? 0xFFFFFFFFu : 0x80000000u;
            unsigned long long k0 = ((unsigned long long)b0 << 6) | (unsigned)(63 - lane);
            unsigned long long k1 = ((unsigned long long)b1 << 6) | (unsigned)(63 - (lane + 32));
            unsigned long long kb = (k0 > k1) ? k0 : k1;
            #pragma unroll
            for (int o = 16; o; o >>= 1) {
                unsigned long long ok = __shfl_xor_sync(0xffffffffu, kb, o);
                if (ok > kb) kb = ok;
            }
            int widx = 63 - (int)(kb & 63);
            float wv = lg[t][widx];
            wid_[k] = widx;
            float ew = __expf(wv - m);
            wex[k] = ew;
            ssum += ew;
            if (widx < 32) { if (lane == widx)      s0 = __int_as_float(0xff800000); }
            else           { if (lane == widx - 32) s1 = __int_as_float(0xff800000); }
        }

        float gs    = ssum / z;
        float denom = fmaxf(gs, 1.1920929e-07f);
        if (lane == 0) {
            int tok = t0 + t;
            #pragma unroll
            for (int k = 0; k < TKK; k++) {
                g_id[tok * TKK + k] = wid_[k];
                g_pr[tok * TKK + k] = wex[k] / (z * denom);
            }
        }
    }

    // ---- last-finishing GEMM block computes bases + positions ----
    __threadfence();
    __syncthreads();
    if (tid == 0) s_last = (atomicAdd(&g_done, 1) == NGEMM - 1);
    __syncthreads();
    if (!s_last) return;

    int* cnt   = (int*)sraw;                       // [8][64]
    int* sbase = (int*)(sraw + 2048);              // [8][64]
    int (*hist)[65] = (int(*)[65])(sraw + 4096);   // [64][65]

    for (int i = tid; i < TKK * EE; i += NTHR) cnt[i] = 0;
    __syncthreads();
    for (int i = tid; i < TT * TKK; i += NTHR) {
        int k = i & 7;
        atomicAdd(&cnt[k * EE + __ldcg(&g_id[i])], 1);
    }
    __syncthreads();
    if (tid < EE) {
        int run = 0;
        #pragma unroll
        for (int k = 0; k < TKK; k++) {
            sbase[k * EE + tid] = run;
            run += cnt[k * EE + tid];
        }
    }
    __syncthreads();

    for (int k = 0; k < TKK; k++) {
        for (int i = tid; i < 64 * 65; i += NTHR) ((int*)hist)[i] = 0;
        __syncthreads();
        for (int i = tid; i < TT; i += NTHR)
            atomicAdd(&hist[i >> 6][__ldcg(&g_id[i * TKK + k])], 1);
        __syncthreads();
        if (tid < 64) {                    // exclusive scan over segments
            int run = 0;
            #pragma unroll
            for (int s = 0; s < 64; s++) {
                int v = hist[s][tid];
                hist[s][tid] = run;
                run += v;
            }
        }
        __syncthreads();
        if (tid < 64) {                    // serial walk within segment
            int s = tid;
            for (int j = 0; j < 64; j++) {
                int t = s * 64 + j;
                int e = __ldcg(&g_id[t * TKK + k]);
                int r = hist[s][e];
                hist[s][e] = r + 1;
                g_pos[t * TKK + k] = sbase[k * EE + e] + r;
            }
        }
        __syncthreads();
    }
}

// ============================================================================
// Kernel C: scatter nonzeros into zeroed output; reset g_done for next replay.
//   out = [combine_weights (T*E*C fp32) ; dispatch_mask as fp32 (T*E*C)]
// ============================================================================
__global__ void __launch_bounds__(256) kC(float* __restrict__ out, int C)
{
    if (blockIdx.x == 0 && threadIdx.x == 0) g_done = 0;
    int i = blockIdx.x * 256 + threadIdx.x;
    if (i >= TT * TKK) return;
    int t = i >> 3;
    int e = g_id[i];
    int p = g_pos[i];
    if (p < C) {
        long long idx = ((long long)t * EE + e) * C + p;
        out[idx] = g_pr[i];
        out[(long long)TT * EE * C + idx] = 1.0f;
    }
}

extern "C" void kernel_launch(void* const* d_in, const int* in_sizes, int n_in,
                              void* d_out, int out_size)
{
    const float* x = (const float*)d_in[0];   // hidden_states [1,4096,4096]
    const float* w = (const float*)d_in[1];   // wg_weight [64,4096]
    float* out = (float*)d_out;

    long long outn = (long long)out_size;
    int C = (int)(outn / (2LL * TT * EE));    // capacity from buffer size

    kA<<<1088, NTHR>>>(x, w, out, outn);      // fill || GEMM+topk+positions
    kC<<<(TT * TKK + 255) / 256, 256>>>(out, C);
}

// round 5
// speedup vs baseline: 2.2227x; 2.2227x over previous
#include <cuda_runtime.h>

#define TT 4096
#define EE 64
#define HH 4096
#define TKK 8
#define NG  64            // GEMM blocks (dedicated SMs)
#define NF  84            // fill blocks (dedicated SMs)

// ---- scratch (device globals; no allocations allowed) ----
__device__ int   g_id[TT * TKK];    // top-8 expert ids per token
__device__ float g_pr[TT * TKK];    // router prob for each selected expert
__device__ int   g_pos[TT * TKK];   // dispatch position within expert capacity
__device__ int   g_base[TKK * EE];  // exclusive prefix of per-(k,e) counts over k

// ============================================================================
// mainA: 148 blocks x 256 thr, SM-partitioned roles.
//   bid <  NG : GEMM 64tok x 64exp tile; K-split2 (two 128-thread halves),
//               thread tile 8tok x 4exp, f32x2 FMA, broadcast LDS layout.
//   bid >= NG : streaming zero-fill of d_out (float4, evict-streaming).
// ============================================================================
__global__ void __launch_bounds__(256, 1) mainA(const float* __restrict__ x,
                                                const float* __restrict__ w,
                                                float* __restrict__ out,
                                                long long outn)
{
    const int bid = blockIdx.x, tid = threadIdx.x;

    if (bid >= NG) {
        // ---------------- fill role ----------------
        float4 z = make_float4(0.f, 0.f, 0.f, 0.f);
        float4* o4 = (float4*)out;
        long long n4 = outn >> 2;
        long long step = (long long)NF * 256;
        long long i = (long long)(bid - NG) * 256 + tid;
        for (; i + 3 * step < n4; i += 4 * step) {
            __stcs(o4 + i, z);
            __stcs(o4 + i + step, z);
            __stcs(o4 + i + 2 * step, z);
            __stcs(o4 + i + 3 * step, z);
        }
        for (; i < n4; i += step) __stcs(o4 + i, z);
        return;
    }

    // ---------------- GEMM role ----------------
    __shared__ __align__(16) float Xs[64 * 66];   // [token][k0..63] stride 66
    __shared__ __align__(16) float Ws[64 * 66];   // [expert][k0..63] stride 66
    float* P = Xs;                                // logits overlay after mainloop

    const int t0   = bid * 64;
    const int half = tid >> 7;        // K-split half
    const int ht   = tid & 127;
    const int tx   = ht & 15;         // expert group: experts tx*4 .. tx*4+3
    const int ty   = ht >> 4;         // token group:  tokens ty*8 .. ty*8+7

    unsigned long long A[16];         // outer accum f32x2: [tok8][epair2]
    #pragma unroll
    for (int i = 0; i < 16; i++) A[i] = 0ull;

    for (int h0 = 0; h0 < HH / 2; h0 += 32) {
        // stage 64 k-rows: r<32 -> half0 (h0+r), r>=32 -> half1 (2048+h0+r-32)
        #pragma unroll
        for (int rr = 0; rr < 16; rr++) {
            int i = rr * 256 + tid;
            int t = i >> 6, r = i & 63;
            int gk = h0 + ((r >> 5) << 11) + (r & 31);
            Xs[t * 66 + r] = x[(long long)(t0 + t) * HH + gk];
            Ws[t * 66 + r] = w[(long long)t * HH + gk];
        }
        __syncthreads();

        unsigned long long c[16];
        #pragma unroll
        for (int i = 0; i < 16; i++) c[i] = 0ull;

        const float* xb = &Xs[(ty * 8) * 66 + half * 32];
        const float* wb = &Ws[(tx * 4) * 66 + half * 32];

        #pragma unroll 4
        for (int kk2 = 0; kk2 < 16; kk2++) {
            float2 xt[8], wt[4];
            #pragma unroll
            for (int j = 0; j < 8; j++) xt[j] = *(const float2*)&xb[j * 66 + kk2 * 2];
            #pragma unroll
            for (int j = 0; j < 4; j++) wt[j] = *(const float2*)&wb[j * 66 + kk2 * 2];

            #pragma unroll
            for (int s = 0; s < 2; s++) {
                float w0 = s ? wt[0].y : wt[0].x;
                float w1 = s ? wt[1].y : wt[1].x;
                float w2 = s ? wt[2].y : wt[2].x;
                float w3 = s ? wt[3].y : wt[3].x;
                unsigned long long wp0, wp1;
                asm("mov.b64 %0, {%1, %2};" : "=l"(wp0)
                    : "r"(__float_as_uint(w0)), "r"(__float_as_uint(w1)));
                asm("mov.b64 %0, {%1, %2};" : "=l"(wp1)
                    : "r"(__float_as_uint(w2)), "r"(__float_as_uint(w3)));
                #pragma unroll
                for (int j = 0; j < 8; j++) {
                    float xv = s ? xt[j].y : xt[j].x;
                    unsigned long long xx;
                    asm("mov.b64 %0, {%1, %1};" : "=l"(xx) : "r"(__float_as_uint(xv)));
                    asm("fma.rn.f32x2 %0, %1, %2, %0;" : "+l"(c[j * 2])     : "l"(wp0), "l"(xx));
                    asm("fma.rn.f32x2 %0, %1, %2, %0;" : "+l"(c[j * 2 + 1]) : "l"(wp1), "l"(xx));
                }
            }
        }
        #pragma unroll
        for (int i = 0; i < 16; i++)
            asm("add.rn.f32x2 %0, %1, %0;" : "+l"(A[i]) : "l"(c[i]));
        __syncthreads();
    }

    // ---- combine K-halves into float logits P[t*66+e] ----
    if (half == 1) {
        #pragma unroll
        for (int j = 0; j < 8; j++)
            #pragma unroll
            for (int p = 0; p < 2; p++) {
                unsigned lo, hi;
                asm("mov.b64 {%0, %1}, %2;" : "=r"(lo), "=r"(hi) : "l"(A[j * 2 + p]));
                P[(ty * 8 + j) * 66 + tx * 4 + 2 * p]     = __uint_as_float(lo);
                P[(ty * 8 + j) * 66 + tx * 4 + 2 * p + 1] = __uint_as_float(hi);
            }
    }
    __syncthreads();
    if (half == 0) {
        #pragma unroll
        for (int j = 0; j < 8; j++)
            #pragma unroll
            for (int p = 0; p < 2; p++) {
                unsigned lo, hi;
                asm("mov.b64 {%0, %1}, %2;" : "=r"(lo), "=r"(hi) : "l"(A[j * 2 + p]));
                int b = (ty * 8 + j) * 66 + tx * 4 + 2 * p;
                P[b]     += __uint_as_float(lo);
                P[b + 1] += __uint_as_float(hi);
            }
    }
    __syncthreads();

    // ---- softmax + iterative top-8 (8 warps x 8 tokens) ----
    const int wrp = tid >> 5, lane = tid & 31;
    for (int tt = 0; tt < 8; tt++) {
        int t = wrp * 8 + tt;
        float v0 = P[t * 66 + lane], v1 = P[t * 66 + lane + 32];

        float m = fmaxf(v0, v1);
        #pragma unroll
        for (int o = 16; o; o >>= 1) m = fmaxf(m, __shfl_xor_sync(0xffffffffu, m, o));

        float z = __expf(v0 - m) + __expf(v1 - m);
        #pragma unroll
        for (int o = 16; o; o >>= 1) z += __shfl_xor_sync(0xffffffffu, z, o);

        float s0 = v0, s1 = v1;
        int   wid_[TKK];
        float wex[TKK];
        float ssum = 0.f;

        #pragma unroll
        for (int k = 0; k < TKK; k++) {
            unsigned b0 = __float_as_uint(s0);
            b0 ^= (b0 & 0x80000000u) ? 0xFFFFFFFFu : 0x80000000u;
            unsigned b1 = __float_as_uint(s1);
            b1 ^= (b1 & 0x80000000u) ? 0xFFFFFFFFu : 0x80000000u;
            unsigned long long k0 = ((unsigned long long)b0 << 6) | (unsigned)(63 - lane);
            unsigned long long k1 = ((unsigned long long)b1 << 6) | (unsigned)(63 - (lane + 32));
            unsigned long long kb = (k0 > k1) ? k0 : k1;
            #pragma unroll
            for (int o = 16; o; o >>= 1) {
                unsigned long long ok = __shfl_xor_sync(0xffffffffu, kb, o);
                if (ok > kb) kb = ok;
            }
            int widx = 63 - (int)(kb & 63);
            float wv = P[t * 66 + widx];
            wid_[k] = widx;
            float ew = __expf(wv - m);
            wex[k] = ew;
            ssum += ew;
            if (widx < 32) { if (lane == widx)      s0 = __int_as_float(0xff800000); }
            else           { if (lane == widx - 32) s1 = __int_as_float(0xff800000); }
        }

        float gs    = ssum / z;
        float denom = fmaxf(gs, 1.1920929e-07f);
        if (lane == 0) {
            int tok = t0 + t;
            #pragma unroll
            for (int k = 0; k < TKK; k++) {
                g_id[tok * TKK + k] = wid_[k];
                g_pr[tok * TKK + k] = wex[k] / (z * denom);
            }
        }
    }
}

// ============================================================================
// kB0: per-(k,e) counts -> exclusive prefix over k. 1 block.
// ============================================================================
__global__ void __launch_bounds__(512) kB0()
{
    __shared__ int cnt[TKK * EE];
    int tid = threadIdx.x;
    for (int i = tid; i < TKK * EE; i += 512) cnt[i] = 0;
    __syncthreads();
    for (int i = tid; i < TT * TKK; i += 512)
        atomicAdd(&cnt[(i & 7) * EE + g_id[i]], 1);
    __syncthreads();
    if (tid < EE) {
        int run = 0;
        #pragma unroll
        for (int k = 0; k < TKK; k++) {
            g_base[k * EE + tid] = run;
            run += cnt[k * EE + tid];
        }
    }
}

// ============================================================================
// kB1: within-expert ranks (one block per k). ids staged in smem, then
//   segment-histogram -> exclusive scan over segments -> serial in-segment walk.
// ============================================================================
__global__ void __launch_bounds__(256) kB1()
{
    const int k = blockIdx.x, tid = threadIdx.x;
    __shared__ int ids[TT];
    __shared__ int hist[64][65];

    for (int i = tid; i < TT; i += 256) ids[i] = g_id[i * TKK + k];
    for (int i = tid; i < 64 * 65; i += 256) ((int*)hist)[i] = 0;
    __syncthreads();

    for (int i = tid; i < TT; i += 256)
        atomicAdd(&hist[i >> 6][ids[i]], 1);
    __syncthreads();

    if (tid < 64) {                       // exclusive scan over segments
        int run = 0;
        #pragma unroll
        for (int s = 0; s < 64; s++) {
            int v = hist[s][tid];
            hist[s][tid] = run;
            run += v;
        }
    }
    __syncthreads();

    if (tid < 64) {                       // serial walk within segment
        int s = tid;
        for (int j = 0; j < 64; j++) {
            int t = s * 64 + j;
            int e = ids[t];
            int r = hist[s][e];
            hist[s][e] = r + 1;
            g_pos[t * TKK + k] = g_base[k * EE + e] + r;
        }
    }
}

// ============================================================================
// kC: scatter 32768 nonzeros into zeroed output.
//   out = [combine_weights (T*E*C fp32) ; dispatch_mask as fp32 (T*E*C)]
// ============================================================================
__global__ void __launch_bounds__(256) kC(float* __restrict__ out, int C)
{
    int i = blockIdx.x * 256 + threadIdx.x;
    if (i >= TT * TKK) return;
    int t = i >> 3;
    int e = g_id[i];
    int p = g_pos[i];
    if (p < C) {
        long long idx = ((long long)t * EE + e) * C + p;
        out[idx] = g_pr[i];
        out[(long long)TT * EE * C + idx] = 1.0f;
    }
}

extern "C" void kernel_launch(void* const* d_in, const int* in_sizes, int n_in,
                              void* d_out, int out_size)
{
    const float* x = (const float*)d_in[0];   // hidden_states [1,4096,4096]
    const float* w = (const float*)d_in[1];   // wg_weight [64,4096]
    float* out = (float*)d_out;

    long long outn = (long long)out_size;
    int C = (int)(outn / (2LL * TT * EE));    // capacity from buffer size

    mainA<<<NG + NF, 256>>>(x, w, out, outn); // SM-partitioned fill || GEMM+top8
    kB0<<<1, 512>>>();
    kB1<<<TKK, 256>>>();
    kC<<<(TT * TKK + 255) / 256, 256>>>(out, C);
}

// round 6
// speedup vs baseline: 3.0640x; 1.3785x over previous
#include <cuda_runtime.h>

#define TT 4096
#define EE 64
#define HH 4096
#define TKK 8
#define NG  64            // GEMM-role blocks (they join fill when done)
#define NB  148           // total blocks = one per SM
#define CHUNK 4096        // float4s per warp fill chunk (64KB)

// ---- scratch (device globals; no allocations allowed) ----
__device__ int   g_id[TT * TKK];    // top-8 expert ids per token
__device__ float g_pr[TT * TKK];    // router prob for each selected expert
__device__ int   g_chunk;           // fill-chunk dispenser (reset by kB)

// ---- warp-level fill: grab 64KB chunks until exhausted ----
__device__ __forceinline__ void fill_warp(float4* __restrict__ o4, long long n4)
{
    const int lane = threadIdx.x & 31;
    const float4 z = make_float4(0.f, 0.f, 0.f, 0.f);
    for (;;) {
        int c = 0;
        if (lane == 0) c = atomicAdd(&g_chunk, 1);
        c = __shfl_sync(0xffffffffu, c, 0);
        long long base = (long long)c * CHUNK;
        if (base >= n4) return;
        if (base + CHUNK <= n4) {
            #pragma unroll 4
            for (int j = 0; j < CHUNK / 32; j++)
                __stcs(o4 + base + lane + j * 32, z);
        } else {
            for (long long i = base + lane; i < n4; i += 32)
                __stcs(o4 + i, z);
        }
    }
}

// ============================================================================
// mainA: 148 blocks x 256 thr.
//   bid <  NG : GEMM 64tok x 64exp tile (K-split2, 8tok x 4exp register tile,
//               f32x2 FMA) + softmax + top-8, THEN joins the fill.
//   bid >= NG : zero-fill role from the start (warp chunk dispenser).
// ============================================================================
__global__ void __launch_bounds__(256, 1) mainA(const float* __restrict__ x,
                                                const float* __restrict__ w,
                                                float* __restrict__ out,
                                                long long outn)
{
    const int bid = blockIdx.x, tid = threadIdx.x;
    long long n4 = outn >> 2;

    if (bid >= NG) {                      // ---------------- fill role
        fill_warp((float4*)out, n4);
        return;
    }

    // ---------------- GEMM role ----------------
    __shared__ __align__(16) float Xs[64 * 66];   // [token][k] stride 66
    __shared__ __align__(16) float Ws[64 * 66];   // [expert][k] stride 66
    float* P = Xs;                                // logits overlay

    const int t0   = bid * 64;
    const int half = tid >> 7;        // K-split half
    const int ht   = tid & 127;
    const int tx   = ht & 15;         // experts tx*4 .. tx*4+3
    const int ty   = ht >> 4;         // tokens  ty*8 .. ty*8+7

    unsigned long long A[16];
    #pragma unroll
    for (int i = 0; i < 16; i++) A[i] = 0ull;

    for (int h0 = 0; h0 < HH / 2; h0 += 32) {
        #pragma unroll
        for (int rr = 0; rr < 16; rr++) {
            int i = rr * 256 + tid;
            int t = i >> 6, r = i & 63;
            int gk = h0 + ((r >> 5) << 11) + (r & 31);
            Xs[t * 66 + r] = x[(long long)(t0 + t) * HH + gk];
            Ws[t * 66 + r] = w[(long long)t * HH + gk];
        }
        __syncthreads();

        unsigned long long c[16];
        #pragma unroll
        for (int i = 0; i < 16; i++) c[i] = 0ull;

        const float* xb = &Xs[(ty * 8) * 66 + half * 32];
        const float* wb = &Ws[(tx * 4) * 66 + half * 32];

        #pragma unroll 4
        for (int kk2 = 0; kk2 < 16; kk2++) {
            float2 xt[8], wt[4];
            #pragma unroll
            for (int j = 0; j < 8; j++) xt[j] = *(const float2*)&xb[j * 66 + kk2 * 2];
            #pragma unroll
            for (int j = 0; j < 4; j++) wt[j] = *(const float2*)&wb[j * 66 + kk2 * 2];

            #pragma unroll
            for (int s = 0; s < 2; s++) {
                float w0 = s ? wt[0].y : wt[0].x;
                float w1 = s ? wt[1].y : wt[1].x;
                float w2 = s ? wt[2].y : wt[2].x;
                float w3 = s ? wt[3].y : wt[3].x;
                unsigned long long wp0, wp1;
                asm("mov.b64 %0, {%1, %2};" : "=l"(wp0)
                    : "r"(__float_as_uint(w0)), "r"(__float_as_uint(w1)));
                asm("mov.b64 %0, {%1, %2};" : "=l"(wp1)
                    : "r"(__float_as_uint(w2)), "r"(__float_as_uint(w3)));
                #pragma unroll
                for (int j = 0; j < 8; j++) {
                    float xv = s ? xt[j].y : xt[j].x;
                    unsigned long long xx;
                    asm("mov.b64 %0, {%1, %1};" : "=l"(xx) : "r"(__float_as_uint(xv)));
                    asm("fma.rn.f32x2 %0, %1, %2, %0;" : "+l"(c[j * 2])     : "l"(wp0), "l"(xx));
                    asm("fma.rn.f32x2 %0, %1, %2, %0;" : "+l"(c[j * 2 + 1]) : "l"(wp1), "l"(xx));
                }
            }
        }
        #pragma unroll
        for (int i = 0; i < 16; i++)
            asm("add.rn.f32x2 %0, %1, %0;" : "+l"(A[i]) : "l"(c[i]));
        __syncthreads();
    }

    // ---- combine K-halves into logits P[t*66+e] ----
    if (half == 1) {
        #pragma unroll
        for (int j = 0; j < 8; j++)
            #pragma unroll
            for (int p = 0; p < 2; p++) {
                unsigned lo, hi;
                asm("mov.b64 {%0, %1}, %2;" : "=r"(lo), "=r"(hi) : "l"(A[j * 2 + p]));
                P[(ty * 8 + j) * 66 + tx * 4 + 2 * p]     = __uint_as_float(lo);
                P[(ty * 8 + j) * 66 + tx * 4 + 2 * p + 1] = __uint_as_float(hi);
            }
    }
    __syncthreads();
    if (half == 0) {
        #pragma unroll
        for (int j = 0; j < 8; j++)
            #pragma unroll
            for (int p = 0; p < 2; p++) {
                unsigned lo, hi;
                asm("mov.b64 {%0, %1}, %2;" : "=r"(lo), "=r"(hi) : "l"(A[j * 2 + p]));
                int b = (ty * 8 + j) * 66 + tx * 4 + 2 * p;
                P[b]     += __uint_as_float(lo);
                P[b + 1] += __uint_as_float(hi);
            }
    }
    __syncthreads();

    // ---- softmax + iterative top-8 (8 warps x 8 tokens) ----
    const int wrp = tid >> 5, lane = tid & 31;
    for (int tt = 0; tt < 8; tt++) {
        int t = wrp * 8 + tt;
        float v0 = P[t * 66 + lane], v1 = P[t * 66 + lane + 32];

        float m = fmaxf(v0, v1);
        #pragma unroll
        for (int o = 16; o; o >>= 1) m = fmaxf(m, __shfl_xor_sync(0xffffffffu, m, o));

        float z = __expf(v0 - m) + __expf(v1 - m);
        #pragma unroll
        for (int o = 16; o; o >>= 1) z += __shfl_xor_sync(0xffffffffu, z, o);

        float s0 = v0, s1 = v1;
        int   wid_[TKK];
        float wex[TKK];
        float ssum = 0.f;

        #pragma unroll
        for (int k = 0; k < TKK; k++) {
            unsigned b0 = __float_as_uint(s0);
            b0 ^= (b0 & 0x80000000u) ? 0xFFFFFFFFu : 0x80000000u;
            unsigned b1 = __float_as_uint(s1);
            b1 ^= (b1 & 0x80000000u) ? 0xFFFFFFFFu : 0x80000000u;
            unsigned long long k0 = ((unsigned long long)b0 << 6) | (unsigned)(63 - lane);
            unsigned long long k1 = ((unsigned long long)b1 << 6) | (unsigned)(63 - (lane + 32));
            unsigned long long kb = (k0 > k1) ? k0 : k1;
            #pragma unroll
            for (int o = 16; o; o >>= 1) {
                unsigned long long ok = __shfl_xor_sync(0xffffffffu, kb, o);
                if (ok > kb) kb = ok;
            }
            int widx = 63 - (int)(kb & 63);
            float wv = P[t * 66 + widx];
            wid_[k] = widx;
            float ew = __expf(wv - m);
            wex[k] = ew;
            ssum += ew;
            if (widx < 32) { if (lane == widx)      s0 = __int_as_float(0xff800000); }
            else           { if (lane == widx - 32) s1 = __int_as_float(0xff800000); }
        }

        float gs    = ssum / z;
        float denom = fmaxf(gs, 1.1920929e-07f);
        if (lane == 0) {
            int tok = t0 + t;
            #pragma unroll
            for (int k = 0; k < TKK; k++) {
                g_id[tok * TKK + k] = wid_[k];
                g_pr[tok * TKK + k] = wex[k] / (z * denom);
            }
        }
    }

    // ---- GEMM done: join the fill ----
    fill_warp((float4*)out, n4);
}

// ============================================================================
// kB: one block per k. Computes exclusive-over-k bases, within-k ranks, and
//   scatters this k's 4096 (combine, mask) entries directly. Resets dispenser.
//   out = [combine_weights (T*E*C fp32) ; dispatch_mask as fp32 (T*E*C)]
// ============================================================================
__global__ void __launch_bounds__(256) kB(float* __restrict__ out, int C)
{
    const int k = blockIdx.x, tid = threadIdx.x;
    __shared__ int ids[TT];
    __shared__ int hist[64][65];
    __shared__ int base[EE];

    if (k == 0 && tid == 0) g_chunk = 0;          // reset for next replay

    for (int i = tid; i < TT; i += 256) ids[i] = g_id[i * TKK + k];
    for (int i = tid; i < 64 * 65; i += 256) ((int*)hist)[i] = 0;
    if (tid < EE) base[tid] = 0;
    __syncthreads();

    // exclusive-over-k base: counts of (k' < k) assignments per expert
    for (int kp = 0; kp < k; kp++)
        for (int i = tid; i < TT; i += 256)
            atomicAdd(&base[g_id[i * TKK + kp]], 1);

    // segment histogram for this k
    for (int i = tid; i < TT; i += 256)
        atomicAdd(&hist[i >> 6][ids[i]], 1);
    __syncthreads();

    if (tid < 64) {                       // exclusive scan over segments
        int run = 0;
        #pragma unroll
        for (int s = 0; s < 64; s++) {
            int v = hist[s][tid];
            hist[s][tid] = run;
            run += v;
        }
    }
    __syncthreads();

    if (tid < 64) {                       // serial in-segment walk + scatter
        long long halfOff = (long long)TT * EE * C;
        int s = tid;
        for (int j = 0; j < 64; j++) {
            int t = s * 64 + j;
            int e = ids[t];
            int r = hist[s][e];
            hist[s][e] = r + 1;
            int p = base[e] + r;
            if (p < C) {
                long long idx = ((long long)t * EE + e) * C + p;
                out[idx]           = g_pr[t * TKK + k];
                out[halfOff + idx] = 1.0f;
            }
        }
    }
}

extern "C" void kernel_launch(void* const* d_in, const int* in_sizes, int n_in,
                              void* d_out, int out_size)
{
    const float* x = (const float*)d_in[0];   // hidden_states [1,4096,4096]
    const float* w = (const float*)d_in[1];   // wg_weight [64,4096]
    float* out = (float*)d_out;

    long long outn = (long long)out_size;
    int C = (int)(outn / (2LL * TT * EE));    // capacity from buffer size

    mainA<<<NB, 256>>>(x, w, out, outn);      // fill (all SMs) || GEMM+top8
    kB<<<TKK, 256>>>(out, C);                 // bases+ranks+scatter, reset
}